// round 3
// baseline (speedup 1.0000x reference)
#include <cuda_runtime.h>
#include <cstdint>
#include <cfloat>

// Problem constants
#define NF    1024          // filters
#define BATCH 1024          // batch
#define HW    64            // H == W
#define PIX   (HW * HW)     // 4096 pixels per image

// 16 MB scratch: X transposed to [pixel][batch] so warps (lanes = batches)
// load contiguous 128B lines.
__device__ float g_xt[(size_t)PIX * BATCH];

// ---------------------------------------------------------------------------
// Kernel 1: transpose X [B, 4096] -> g_xt [4096, B]
// ---------------------------------------------------------------------------
__global__ void xt_transpose_kernel(const float* __restrict__ X) {
    __shared__ float tile[32][33];
    const int p0 = blockIdx.x * 32;   // pixel tile origin
    const int b0 = blockIdx.y * 32;   // batch tile origin
    const int tx = threadIdx.x;
    const int ty = threadIdx.y;
#pragma unroll
    for (int k = 0; k < 32; k += 8)
        tile[ty + k][tx] = X[(size_t)(b0 + ty + k) * PIX + (p0 + tx)];
    __syncthreads();
#pragma unroll
    for (int k = 0; k < 32; k += 8)
        g_xt[(size_t)(p0 + ty + k) * BATCH + (b0 + tx)] = tile[tx][ty + k];
}

// ---------------------------------------------------------------------------
// Packed f32x2 helpers (Blackwell packed-FP32 pipe: 2x FFMA throughput)
// ---------------------------------------------------------------------------
__device__ __forceinline__ unsigned long long ffma2(unsigned long long a,
                                                    unsigned long long b,
                                                    unsigned long long c) {
    unsigned long long d;
    asm("fma.rn.f32x2 %0, %1, %2, %3;" : "=l"(d) : "l"(a), "l"(b), "l"(c));
    return d;
}
__device__ __forceinline__ unsigned long long pack2(float x, float y) {
    unsigned long long r;
    asm("mov.b64 %0, {%1, %2};" : "=l"(r) : "f"(x), "f"(y));
    return r;
}
__device__ __forceinline__ float2 unpack2(unsigned long long v) {
    float2 r;
    asm("mov.b64 {%0, %1}, %2;" : "=f"(r.x), "=f"(r.y) : "l"(v));
    return r;
}

// ---------------------------------------------------------------------------
// Kernel 2: per (filter, batch-pair) fused window-gather + 5x5 conv (6x6 of
// the 7x7 outputs; pool never reads row/col 6) + bias + 3x3/3 maxpool.
// Each thread processes TWO adjacent batches via packed f32x2 math.
// ---------------------------------------------------------------------------
__global__ void __launch_bounds__(128) filters_conv_kernel(
    const float* __restrict__ W,      // [NF, 25]
    const float* __restrict__ bias,   // [NF]
    const int*   __restrict__ pos,    // [NF, 2] (i = row, j = col)
    float*       __restrict__ out)    // [B, NF*4]
{
    const int f = blockIdx.x;
    const int b = blockIdx.y * 256 + threadIdx.x * 2;  // even -> 8B aligned loads
    const int pi = pos[2 * f];
    const int pj = pos[2 * f + 1];

    // Broadcast-pack the 25 weights: (w, w) pairs held in registers.
    unsigned long long wp[25];
#pragma unroll
    for (int k = 0; k < 25; k++) {
        const float w = __ldg(&W[f * 25 + k]);
        wp[k] = pack2(w, w);
    }

    // 6x6 packed accumulators (lane .x = batch b, lane .y = batch b+1).
    unsigned long long acc[36];
#pragma unroll
    for (int k = 0; k < 36; k++) acc[k] = 0ULL;

    // Stream the 10 needed window rows. Padded-window row r maps to image
    // row y = pi + r - 3 (zero outside [0,64)).
#pragma unroll
    for (int r = 0; r < 10; r++) {
        const int y = pi + r - 3;
        const bool yok = ((unsigned)y < (unsigned)HW);

        unsigned long long row[10];
#pragma unroll
        for (int c = 0; c < 10; c++) {
            const int x = pj + c - 3;
            unsigned long long v = 0ULL;
            if (yok && ((unsigned)x < (unsigned)HW)) {
                v = *(const unsigned long long*)(g_xt +
                        ((size_t)(y * HW + x) * BATCH + b));
            }
            row[c] = v;
        }

        // Row r contributes to conv rows oy with ky = r - oy in [0,4].
#pragma unroll
        for (int oy = 0; oy < 6; oy++) {
            const int ky = r - oy;
            if (ky < 0 || ky > 4) continue;   // resolved at compile time
#pragma unroll
            for (int ox = 0; ox < 6; ox++) {
#pragma unroll
                for (int kx = 0; kx < 5; kx++) {
                    acc[oy * 6 + ox] =
                        ffma2(row[ox + kx], wp[ky * 5 + kx], acc[oy * 6 + ox]);
                }
            }
        }
    }

    // Fused bias + 3x3 stride-3 maxpool -> 2x2, then one float4 per batch.
    const float bv = __ldg(&bias[f]);
    float m0[4], m1[4];
#pragma unroll
    for (int py = 0; py < 2; py++) {
#pragma unroll
        for (int px = 0; px < 2; px++) {
            float a0 = -FLT_MAX, a1 = -FLT_MAX;
#pragma unroll
            for (int dy = 0; dy < 3; dy++) {
#pragma unroll
                for (int dx = 0; dx < 3; dx++) {
                    const float2 v =
                        unpack2(acc[(3 * py + dy) * 6 + (3 * px + dx)]);
                    a0 = fmaxf(a0, v.x);
                    a1 = fmaxf(a1, v.y);
                }
            }
            m0[py * 2 + px] = a0 + bv;
            m1[py * 2 + px] = a1 + bv;
        }
    }

    // out[b, f*4 + py*2 + px]; row stride NF*4 = 4096 floats; 16B aligned.
    float4* o0 = (float4*)(out + (size_t)b * (NF * 4) + f * 4);
    float4* o1 = (float4*)(out + (size_t)(b + 1) * (NF * 4) + f * 4);
    *o0 = make_float4(m0[0], m0[1], m0[2], m0[3]);
    *o1 = make_float4(m1[0], m1[1], m1[2], m1[3]);
}

// ---------------------------------------------------------------------------
// kernel_launch: transpose then fused conv. Graph-capturable: two plain
// launches, no sync, no allocation (scratch is a __device__ global).
// ---------------------------------------------------------------------------
extern "C" void kernel_launch(void* const* d_in, const int* in_sizes, int n_in,
                              void* d_out, int out_size) {
    (void)in_sizes; (void)n_in; (void)out_size;
    const float* X    = (const float*)d_in[0];
    const float* W    = (const float*)d_in[1];
    const float* bias = (const float*)d_in[2];
    const int*   pos  = (const int*)d_in[3];
    float*       out  = (float*)d_out;

    dim3 tb(32, 8);
    dim3 tg(PIX / 32, BATCH / 32);         // (128, 32)
    xt_transpose_kernel<<<tg, tb>>>(X);

    dim3 cg(NF, BATCH / 256);              // (1024, 4)
    filters_conv_kernel<<<cg, 128>>>(W, bias, pos, out);
}

// round 4
// speedup vs baseline: 1.0321x; 1.0321x over previous
#include <cuda_runtime.h>
#include <cstdint>
#include <cfloat>

// Problem constants
#define NF    1024          // filters
#define BATCH 1024          // batch
#define HW    64            // H == W
#define PIX   (HW * HW)     // 4096 pixels per image
#define PAD   3
#define PW    70            // padded side: 64 + 2*3
#define PPIX  (PW * PW)     // 4900 padded pixels

// 20 MB scratch: zero-PADDED image transposed to [padded_pixel][batch] so
// warps (lanes = batches) load contiguous lines and the conv loop needs NO
// bounds checks and NO per-load address math (immediate offsets only).
__device__ float g_xt[(size_t)PPIX * BATCH];

// ---------------------------------------------------------------------------
// Kernel 0: zero the padded border lines of g_xt (interior overwritten by
// the transpose). One block per padded pixel; interior blocks exit early.
// ---------------------------------------------------------------------------
__global__ void border_zero_kernel() {
    const int p = blockIdx.x;            // 0 .. 4899
    const int r = p / PW, c = p % PW;
    if (r >= PAD && r < PAD + HW && c >= PAD && c < PAD + HW) return;
    float4* dst = (float4*)(g_xt + (size_t)p * BATCH) + threadIdx.x;
    *dst = make_float4(0.f, 0.f, 0.f, 0.f);
}

// ---------------------------------------------------------------------------
// Kernel 1: transpose X [B, 4096] -> interior of g_xt [4900, B]
// ---------------------------------------------------------------------------
__global__ void xt_transpose_kernel(const float* __restrict__ X) {
    __shared__ float tile[32][33];
    const int p0 = blockIdx.x * 32;      // pixel tile origin (image coords)
    const int b0 = blockIdx.y * 32;      // batch tile origin
    const int tx = threadIdx.x;
    const int ty = threadIdx.y;
#pragma unroll
    for (int k = 0; k < 32; k += 8)
        tile[ty + k][tx] = X[(size_t)(b0 + ty + k) * PIX + (p0 + tx)];
    __syncthreads();
#pragma unroll
    for (int k = 0; k < 32; k += 8) {
        const int p = p0 + ty + k;
        const int y = p >> 6, x = p & 63;
        g_xt[(size_t)((y + PAD) * PW + (x + PAD)) * BATCH + (b0 + tx)] =
            tile[tx][ty + k];
    }
}

// ---------------------------------------------------------------------------
// Packed f32x2 helpers (Blackwell packed-FP32 pipe: 2x FFMA throughput)
// ---------------------------------------------------------------------------
__device__ __forceinline__ unsigned long long ffma2(unsigned long long a,
                                                    unsigned long long b,
                                                    unsigned long long c) {
    unsigned long long d;
    asm("fma.rn.f32x2 %0, %1, %2, %3;" : "=l"(d) : "l"(a), "l"(b), "l"(c));
    return d;
}
__device__ __forceinline__ unsigned long long pack2(float x, float y) {
    unsigned long long r;
    asm("mov.b64 %0, {%1, %2};" : "=l"(r) : "f"(x), "f"(y));
    return r;
}
__device__ __forceinline__ float2 unpack2(unsigned long long v) {
    float2 r;
    asm("mov.b64 {%0, %1}, %2;" : "=f"(r.x), "=f"(r.y) : "l"(v));
    return r;
}

// ---------------------------------------------------------------------------
// Kernel 2: per (filter, batch-pair) fused window-gather + 5x5 conv (only the
// 6x6 of the 7x7 outputs the pool reads) + bias + 3x3/3 maxpool.
// Each thread: 2 adjacent batches as one f32x2 lane pair.
// All 100 loads are LDG [ptr0 + compile-time-immediate]; no predicates.
// ---------------------------------------------------------------------------
__global__ void __launch_bounds__(128, 3) filters_conv_kernel(
    const float* __restrict__ W,      // [NF, 25]
    const float* __restrict__ bias,   // [NF]
    const int*   __restrict__ pos,    // [NF, 2] (i = row, j = col)
    float*       __restrict__ out)    // [B, NF*4]
{
    const int f = blockIdx.x;
    const int b = blockIdx.y * 256 + threadIdx.x * 2;  // even -> 8B aligned
    const int pi = __ldg(&pos[2 * f]);
    const int pj = __ldg(&pos[2 * f + 1]);

    // Single base pointer; every load below uses a constant byte offset.
    const char* p0 = (const char*)g_xt +
                     ((size_t)(pi * PW + pj) * BATCH + b) * sizeof(float);

    // Broadcast-pack the 25 weights into (w, w) register pairs.
    unsigned long long wp[25];
#pragma unroll
    for (int k = 0; k < 25; k++) {
        const float w = __ldg(&W[f * 25 + k]);
        wp[k] = pack2(w, w);
    }

    // 6x6 packed accumulators (lane .x = batch b, lane .y = batch b+1).
    unsigned long long acc[36];
#pragma unroll
    for (int k = 0; k < 36; k++) acc[k] = 0ULL;

    // Stream the 10 window rows of the zero-padded image.
#pragma unroll
    for (int r = 0; r < 10; r++) {
        unsigned long long row[10];
#pragma unroll
        for (int c = 0; c < 10; c++)
            row[c] = *(const unsigned long long*)(
                p0 + (size_t)((r * PW + c) * BATCH) * sizeof(float));

        // Row r feeds conv rows oy with ky = r - oy in [0,4].
#pragma unroll
        for (int oy = 0; oy < 6; oy++) {
            const int ky = r - oy;
            if (ky < 0 || ky > 4) continue;   // compile-time pruned
#pragma unroll
            for (int ox = 0; ox < 6; ox++) {
#pragma unroll
                for (int kx = 0; kx < 5; kx++) {
                    acc[oy * 6 + ox] =
                        ffma2(row[ox + kx], wp[ky * 5 + kx], acc[oy * 6 + ox]);
                }
            }
        }
    }

    // Fused bias + 3x3 stride-3 maxpool -> 2x2, one float4 per batch.
    const float bv = __ldg(&bias[f]);
    float m0[4], m1[4];
#pragma unroll
    for (int py = 0; py < 2; py++) {
#pragma unroll
        for (int px = 0; px < 2; px++) {
            float a0 = -FLT_MAX, a1 = -FLT_MAX;
#pragma unroll
            for (int dy = 0; dy < 3; dy++) {
#pragma unroll
                for (int dx = 0; dx < 3; dx++) {
                    const float2 v =
                        unpack2(acc[(3 * py + dy) * 6 + (3 * px + dx)]);
                    a0 = fmaxf(a0, v.x);
                    a1 = fmaxf(a1, v.y);
                }
            }
            m0[py * 2 + px] = a0 + bv;
            m1[py * 2 + px] = a1 + bv;
        }
    }

    float4* o0 = (float4*)(out + (size_t)b * (NF * 4) + f * 4);
    float4* o1 = (float4*)(out + (size_t)(b + 1) * (NF * 4) + f * 4);
    *o0 = make_float4(m0[0], m0[1], m0[2], m0[3]);
    *o1 = make_float4(m1[0], m1[1], m1[2], m1[3]);
}

// ---------------------------------------------------------------------------
// kernel_launch: border-zero + transpose + fused conv. Graph-capturable:
// plain launches only, no sync, no allocation (scratch is a __device__ global).
// ---------------------------------------------------------------------------
extern "C" void kernel_launch(void* const* d_in, const int* in_sizes, int n_in,
                              void* d_out, int out_size) {
    (void)in_sizes; (void)n_in; (void)out_size;
    const float* X    = (const float*)d_in[0];
    const float* W    = (const float*)d_in[1];
    const float* bias = (const float*)d_in[2];
    const int*   pos  = (const int*)d_in[3];
    float*       out  = (float*)d_out;

    border_zero_kernel<<<PPIX, BATCH / 4>>>();

    dim3 tb(32, 8);
    dim3 tg(PIX / 32, BATCH / 32);         // (128, 32)
    xt_transpose_kernel<<<tg, tb>>>(X);

    dim3 cg(NF, BATCH / 256);              // (1024, 4)
    filters_conv_kernel<<<cg, 128>>>(W, bias, pos, out);
}